// round 6
// baseline (speedup 1.0000x reference)
#include <cuda_runtime.h>
#include <cuda_fp16.h>

// Problem constants
#define B_TOTAL   16384
#define N_IN      6
#define N_MF      5
#define N_FUZZ    30      // N_IN * N_MF
#define N_RULES   2048
#define N_OUT     2

// Main-kernel tiling: 128 rows/block, 4 rows/thread (uint2 = 2x half2),
// rules split into 2 halves across blockIdx.y -> 2 co-resident blocks/SM.
#define THREADS   1024
#define ROWS      128
#define QUADS     32                    // ROWS/4
#define PARTS     32                    // THREADS / QUADS
#define N_HALF    (N_RULES / 2)         // 1024 rules per block
#define RPP       (N_HALF / PARTS)      // 32 rules per thread

// Shared memory layout (dynamic). Reduction buffer OVERLAPS the rule buffer.
#define SMEM_FUZZ_BYTES   (N_FUZZ * QUADS * 8)           // 7680  (uint2 table)
#define SMEM_RULE_BYTES   (N_HALF * 16)                  // 16384
#define SMEM_RED_BYTES    (QUADS * PARTS * 12 * 4)       // 49152
#define SMEM_TOTAL        (SMEM_FUZZ_BYTES + SMEM_RED_BYTES)   // 56832 (x2 = 113.7KB/SM)

// Per-(half, row) partial results: x=L1, y=D0, z=D1. Static device scratch.
__device__ float4 g_partial[2][B_TOTAL];

// ---------------------------------------------------------------------------
// Main kernel: block (tile, half) processes 128 rows x 1024 rules.
// ---------------------------------------------------------------------------
__global__ void __launch_bounds__(THREADS, 2) anfis_main_kernel(
    const float* __restrict__ x,
    const float* __restrict__ mf_centers,
    const float* __restrict__ mf_scales,
    const float* __restrict__ out_centers,
    const int*   __restrict__ input_rules,
    const int*   __restrict__ output_rules)
{
    extern __shared__ char smem[];
    uint2*  s_fuzz  = reinterpret_cast<uint2*>(smem);                       // [30][32]
    float4* s_rules = reinterpret_cast<float4*>(smem + SMEM_FUZZ_BYTES);    // [1024] (dies after loop)
    float*  s_red   = reinterpret_cast<float*>(smem + SMEM_FUZZ_BYTES);     // overlaps rules

    const int tid  = threadIdx.x;
    const int quad = tid & (QUADS - 1);   // row-quad (0..31)
    const int part = tid >> 5;            // rule partition (0..31)
    const int tile = blockIdx.x;          // row tile (0..127)
    const int half = blockIdx.y;          // rule half (0..1)

    // ---- phase 0: pack this block's 1024 rules into smem (1 per thread) ----
    {
        const int rg = half * N_HALF + tid;     // global rule id
        unsigned int b0 = 0, b1 = 0;
#pragma unroll
        for (int k = 0; k < 4; k++)
            b0 |= ((unsigned int)input_rules[rg * N_IN + k] & 0xFFu) << (8 * k);
#pragma unroll
        for (int k = 0; k < 2; k++)
            b1 |= ((unsigned int)input_rules[rg * N_IN + 4 + k] & 0xFFu) << (8 * k);
        float4 rv;
        rv.x = __uint_as_float(b0);
        rv.y = __uint_as_float(b1);
        rv.z = out_centers[output_rules[rg * N_OUT + 0]];
        rv.w = out_centers[output_rules[rg * N_OUT + 1]];
        s_rules[tid] = rv;
    }

    // ---- phase 1: fuzzify (first 128 threads, one row each) ----
    if (tid < ROWS) {
        const int row = tile * ROWS + tid;
        const int q   = tid >> 2;       // quad index
        const int h   = tid & 3;        // slot within quad
        __half* fzh = reinterpret_cast<__half*>(s_fuzz);
        float xv[N_IN];
#pragma unroll
        for (int i = 0; i < N_IN; i++) xv[i] = x[row * N_IN + i];
#pragma unroll
        for (int i = 0; i < N_IN; i++) {
#pragma unroll
            for (int m = 0; m < N_MF; m++) {
                float c = mf_centers[i * N_MF + m];
                float s = mf_scales[i * N_MF + m];
                float z = (xv[i] - c) / s;
                fzh[((i * N_MF + m) * QUADS + q) * 4 + h] = __float2half_rn(__expf(-z * z));
            }
        }
    }
    __syncthreads();

    // ---- phase 2: rule loop. LDS.64 gathers (conflict-free), 2x hmin2 trees ----
    const uint2* fz = s_fuzz + quad;

    float l1a = 0.f, l1b = 0.f, l1c = 0.f, l1d = 0.f;
    float d0a = 0.f, d0b = 0.f, d0c = 0.f, d0d = 0.f;
    float d1a = 0.f, d1b = 0.f, d1c = 0.f, d1d = 0.f;

    const int rbeg = part * RPP;
#pragma unroll 4
    for (int r = rbeg; r < rbeg + RPP; r++) {
        float4 rv = s_rules[r];                         // LDS.128 warp-uniform broadcast
        unsigned int b0 = __float_as_uint(rv.x);
        unsigned int b1 = __float_as_uint(rv.y);

        uint2 g0 = fz[__byte_perm(b0, 0, 0x4440) * QUADS];
        uint2 g1 = fz[__byte_perm(b0, 0, 0x4441) * QUADS];
        uint2 g2 = fz[__byte_perm(b0, 0, 0x4442) * QUADS];
        uint2 g3 = fz[__byte_perm(b0, 0, 0x4443) * QUADS];
        uint2 g4 = fz[__byte_perm(b1, 0, 0x4440) * QUADS];
        uint2 g5 = fz[__byte_perm(b1, 0, 0x4441) * QUADS];

        __half2 mx = __hmin2(__hmin2(__hmin2(*(__half2*)&g0.x, *(__half2*)&g1.x),
                                     __hmin2(*(__half2*)&g2.x, *(__half2*)&g3.x)),
                             __hmin2(*(__half2*)&g4.x, *(__half2*)&g5.x));
        __half2 my = __hmin2(__hmin2(__hmin2(*(__half2*)&g0.y, *(__half2*)&g1.y),
                                     __hmin2(*(__half2*)&g2.y, *(__half2*)&g3.y)),
                             __hmin2(*(__half2*)&g4.y, *(__half2*)&g5.y));

        float2 wx = __half22float2(mx);
        float2 wy = __half22float2(my);

        l1a += wx.x;  l1b += wx.y;  l1c += wy.x;  l1d += wy.y;   // weights > 0
        d0a = fmaf(wx.x, rv.z, d0a);  d0b = fmaf(wx.y, rv.z, d0b);
        d0c = fmaf(wy.x, rv.z, d0c);  d0d = fmaf(wy.y, rv.z, d0d);
        d1a = fmaf(wx.x, rv.w, d1a);  d1b = fmaf(wx.y, rv.w, d1b);
        d1c = fmaf(wy.x, rv.w, d1c);  d1d = fmaf(wy.y, rv.w, d1d);
    }

    // Rules region is dead; reduction buffer overlaps it.
    __syncthreads();

    // ---- phase 3: cross-partition reduction, then write per-half partials ----
    {
        float* dst = s_red + (quad * PARTS + part) * 12;
        dst[0] = l1a; dst[1]  = l1b; dst[2]  = l1c; dst[3]  = l1d;
        dst[4] = d0a; dst[5]  = d0b; dst[6]  = d0c; dst[7]  = d0d;
        dst[8] = d1a; dst[9]  = d1b; dst[10] = d1c; dst[11] = d1d;
    }
    __syncthreads();

    if (tid < ROWS) {
        const int row = tid;
        const int q   = row >> 2;
        const int sub = row & 3;
        float L = 0.f, D0 = 0.f, D1 = 0.f;
#pragma unroll
        for (int p = 0; p < PARTS; p++) {
            const float* src = s_red + (q * PARTS + p) * 12;
            L  += src[0 + sub];
            D0 += src[4 + sub];
            D1 += src[8 + sub];
        }
        g_partial[half][tile * ROWS + row] = make_float4(L, D0, D1, 0.f);
    }
}

// ---------------------------------------------------------------------------
// Finisher: combine the two rule-halves, apply tanh head.
// ---------------------------------------------------------------------------
__global__ void __launch_bounds__(256) anfis_finish_kernel(float* __restrict__ out)
{
    const int row = blockIdx.x * 256 + threadIdx.x;
    float4 a = g_partial[0][row];
    float4 b = g_partial[1][row];
    float L  = a.x + b.x;
    float D0 = a.y + b.y;
    float D1 = a.z + b.z;
    float inv = 1.0f / fmaxf(L, 1e-12f);
    out[row * 2 + 0] = tanhf(D0 * inv) * 4.0f;            // scale 4.0, center 0.0
    out[row * 2 + 1] = tanhf(D1 * inv) * 0.75f + 0.75f;   // scale 0.75, center 0.75
}

// ---------------------------------------------------------------------------
// Launch contract
// ---------------------------------------------------------------------------
extern "C" void kernel_launch(void* const* d_in, const int* in_sizes, int n_in,
                              void* d_out, int out_size)
{
    const float* x            = (const float*)d_in[0];
    const float* mf_centers   = (const float*)d_in[1];
    const float* mf_scales    = (const float*)d_in[2];
    const float* out_centers  = (const float*)d_in[3];
    const int*   input_rules  = (const int*)d_in[4];
    const int*   output_rules = (const int*)d_in[5];
    float*       out          = (float*)d_out;

    // Opt-in to >48KB dynamic smem (immediate API call; capture-safe, no alloc)
    static bool attr_set = false;
    if (!attr_set) {
        cudaFuncSetAttribute(anfis_main_kernel,
                             cudaFuncAttributeMaxDynamicSharedMemorySize, SMEM_TOTAL);
        attr_set = true;
    }

    dim3 grid(B_TOTAL / ROWS, 2);   // 128 row tiles x 2 rule halves = 256 blocks
    anfis_main_kernel<<<grid, THREADS, SMEM_TOTAL>>>(
        x, mf_centers, mf_scales, out_centers, input_rules, output_rules);
    anfis_finish_kernel<<<B_TOTAL / 256, 256>>>(out);
}

// round 7
// speedup vs baseline: 1.0714x; 1.0714x over previous
#include <cuda_runtime.h>
#include <cuda_fp16.h>

// Problem constants
#define B_TOTAL   16384
#define N_IN      6
#define N_MF      5
#define N_FUZZ    30      // N_IN * N_MF
#define N_RULES   2048
#define N_OUT     2

// Tiling: 128 rows/block, 8 rows per thread (uint4 = 4x half2)
#define THREADS   1024
#define ROWS      128
#define OCTS      16                    // ROWS/8
#define PARTS     64                    // THREADS / OCTS
#define RPP       (N_RULES / PARTS)     // 32 rules per thread
#define RED_GRP   8                     // stage-A groups (PARTS/RED_GRP sums each)

// Shared memory layout (dynamic). Rule buffer overlaps the reduction buffer
// (rules are dead after the rule loop; sync-separated).
#define SMEM_FUZZ_BYTES   (N_FUZZ * OCTS * 16)                 // 7680 (uint4 table)
#define SMEM_RULE_BYTES   (N_RULES * 16)                       // 32768
#define SMEM_RED_BYTES    (OCTS * PARTS * 24 * 4)              // 98304
#define SMEM_RED2_BYTES   (ROWS * RED_GRP * 3 * 4)             // 12288
#define SMEM_TOTAL        (SMEM_FUZZ_BYTES + SMEM_RED_BYTES + SMEM_RED2_BYTES) // 118272

// ---------------------------------------------------------------------------
// Single fused kernel.
// ---------------------------------------------------------------------------
__global__ void __launch_bounds__(THREADS, 1) anfis_fused_kernel(
    const float* __restrict__ x,
    const float* __restrict__ mf_centers,
    const float* __restrict__ mf_scales,
    const float* __restrict__ out_centers,
    const int*   __restrict__ input_rules,
    const int*   __restrict__ output_rules,
    float* __restrict__ out)
{
    extern __shared__ char smem[];
    uint4*  s_fuzz  = reinterpret_cast<uint4*>(smem);                       // [30][16]
    float4* s_rules = reinterpret_cast<float4*>(smem + SMEM_FUZZ_BYTES);    // [2048] (dies after loop)
    float*  s_red   = reinterpret_cast<float*>(smem + SMEM_FUZZ_BYTES);     // overlaps rules
    float*  s_red2  = reinterpret_cast<float*>(smem + SMEM_FUZZ_BYTES + SMEM_RED_BYTES);

    const int tid = threadIdx.x;
    const int oct  = tid & (OCTS - 1);    // row-oct (0..15)
    const int part = tid >> 4;            // rule partition (0..63)

    // ---- phase 0: pack rules into smem (2 per thread) ----
#pragma unroll
    for (int rr = 0; rr < N_RULES / THREADS; rr++) {
        int r = tid + rr * THREADS;
        unsigned int b0 = 0, b1 = 0;
#pragma unroll
        for (int k = 0; k < 4; k++)
            b0 |= ((unsigned int)input_rules[r * N_IN + k] & 0xFFu) << (8 * k);
#pragma unroll
        for (int k = 0; k < 2; k++)
            b1 |= ((unsigned int)input_rules[r * N_IN + 4 + k] & 0xFFu) << (8 * k);
        float4 rv;
        rv.x = __uint_as_float(b0);
        rv.y = __uint_as_float(b1);
        rv.z = out_centers[output_rules[r * N_OUT + 0]];
        rv.w = out_centers[output_rules[r * N_OUT + 1]];
        s_rules[r] = rv;
    }

    // ---- phase 1: fuzzify (first 128 threads, one row each) ----
    if (tid < ROWS) {
        const int row = blockIdx.x * ROWS + tid;
        const int q   = tid >> 3;       // oct index
        const int h   = tid & 7;        // slot within oct
        __half* fzh = reinterpret_cast<__half*>(s_fuzz);
        float xv[N_IN];
#pragma unroll
        for (int i = 0; i < N_IN; i++) xv[i] = x[row * N_IN + i];
#pragma unroll
        for (int i = 0; i < N_IN; i++) {
#pragma unroll
            for (int m = 0; m < N_MF; m++) {
                float c = mf_centers[i * N_MF + m];
                float s = mf_scales[i * N_MF + m];
                float z = (xv[i] - c) / s;
                fzh[((i * N_MF + m) * OCTS + q) * 8 + h] = __float2half_rn(__expf(-z * z));
            }
        }
    }
    __syncthreads();

    // ---- phase 2: rule loop. LDS.128 gathers (conflict-free), hmin2 trees ----
    const uint4* fz = s_fuzz + oct;

    float l1[8], d0[8], d1[8];
#pragma unroll
    for (int i = 0; i < 8; i++) { l1[i] = 0.f; d0[i] = 0.f; d1[i] = 0.f; }

    const int rbeg = part * RPP;
#pragma unroll 2
    for (int r = rbeg; r < rbeg + RPP; r++) {
        float4 rv = s_rules[r];                         // half-warp-uniform LDS.128
        unsigned int b0 = __float_as_uint(rv.x);
        unsigned int b1 = __float_as_uint(rv.y);

        uint4 g = fz[__byte_perm(b0, 0, 0x4440) * OCTS];
        __half2 m0 = *(__half2*)&g.x, m1 = *(__half2*)&g.y;
        __half2 m2 = *(__half2*)&g.z, m3 = *(__half2*)&g.w;

        g = fz[__byte_perm(b0, 0, 0x4441) * OCTS];
        m0 = __hmin2(m0, *(__half2*)&g.x); m1 = __hmin2(m1, *(__half2*)&g.y);
        m2 = __hmin2(m2, *(__half2*)&g.z); m3 = __hmin2(m3, *(__half2*)&g.w);

        g = fz[__byte_perm(b0, 0, 0x4442) * OCTS];
        m0 = __hmin2(m0, *(__half2*)&g.x); m1 = __hmin2(m1, *(__half2*)&g.y);
        m2 = __hmin2(m2, *(__half2*)&g.z); m3 = __hmin2(m3, *(__half2*)&g.w);

        g = fz[__byte_perm(b0, 0, 0x4443) * OCTS];
        m0 = __hmin2(m0, *(__half2*)&g.x); m1 = __hmin2(m1, *(__half2*)&g.y);
        m2 = __hmin2(m2, *(__half2*)&g.z); m3 = __hmin2(m3, *(__half2*)&g.w);

        g = fz[__byte_perm(b1, 0, 0x4440) * OCTS];
        m0 = __hmin2(m0, *(__half2*)&g.x); m1 = __hmin2(m1, *(__half2*)&g.y);
        m2 = __hmin2(m2, *(__half2*)&g.z); m3 = __hmin2(m3, *(__half2*)&g.w);

        g = fz[__byte_perm(b1, 0, 0x4441) * OCTS];
        m0 = __hmin2(m0, *(__half2*)&g.x); m1 = __hmin2(m1, *(__half2*)&g.y);
        m2 = __hmin2(m2, *(__half2*)&g.z); m3 = __hmin2(m3, *(__half2*)&g.w);

        float2 w0 = __half22float2(m0);
        float2 w1 = __half22float2(m1);
        float2 w2 = __half22float2(m2);
        float2 w3 = __half22float2(m3);
        float w[8] = { w0.x, w0.y, w1.x, w1.y, w2.x, w2.y, w3.x, w3.y };

#pragma unroll
        for (int i = 0; i < 8; i++) {
            l1[i] += w[i];                      // weights > 0
            d0[i] = fmaf(w[i], rv.z, d0[i]);
            d1[i] = fmaf(w[i], rv.w, d1[i]);
        }
    }

    // Rules region is dead; reduction buffer overlaps it.
    __syncthreads();

    // ---- phase 3a: dump per-thread partials ----
    {
        float* dst = s_red + (oct * PARTS + part) * 24;
#pragma unroll
        for (int i = 0; i < 8; i++) {
            dst[i]      = l1[i];
            dst[8 + i]  = d0[i];
            dst[16 + i] = d1[i];
        }
    }
    __syncthreads();

    // ---- phase 3b: stage A — 1024 threads: each sums 8 partitions for one row ----
    {
        const int row = tid >> 3;            // 0..127
        const int k   = tid & 7;             // group 0..7
        const int q   = row >> 3;
        const int sub = row & 7;
        float L = 0.f, D0 = 0.f, D1 = 0.f;
#pragma unroll
        for (int pp = 0; pp < PARTS / RED_GRP; pp++) {
            const float* src = s_red + (q * PARTS + (k * (PARTS / RED_GRP) + pp)) * 24;
            L  += src[0 + sub];
            D0 += src[8 + sub];
            D1 += src[16 + sub];
        }
        float* dst = s_red2 + (row * RED_GRP + k) * 3;
        dst[0] = L; dst[1] = D0; dst[2] = D1;
    }
    __syncthreads();

    // ---- phase 3c: stage B — 128 threads finish + tanh head ----
    if (tid < ROWS) {
        float L = 0.f, D0 = 0.f, D1 = 0.f;
#pragma unroll
        for (int k = 0; k < RED_GRP; k++) {
            const float* src = s_red2 + (tid * RED_GRP + k) * 3;
            L += src[0]; D0 += src[1]; D1 += src[2];
        }
        float inv = 1.0f / fmaxf(L, 1e-12f);
        const int grow = blockIdx.x * ROWS + tid;
        out[grow * 2 + 0] = tanhf(D0 * inv) * 4.0f;            // scale 4.0, center 0.0
        out[grow * 2 + 1] = tanhf(D1 * inv) * 0.75f + 0.75f;   // scale 0.75, center 0.75
    }
}

// ---------------------------------------------------------------------------
// Launch contract
// ---------------------------------------------------------------------------
extern "C" void kernel_launch(void* const* d_in, const int* in_sizes, int n_in,
                              void* d_out, int out_size)
{
    const float* x            = (const float*)d_in[0];
    const float* mf_centers   = (const float*)d_in[1];
    const float* mf_scales    = (const float*)d_in[2];
    const float* out_centers  = (const float*)d_in[3];
    const int*   input_rules  = (const int*)d_in[4];
    const int*   output_rules = (const int*)d_in[5];
    float*       out          = (float*)d_out;

    // Opt-in to >48KB dynamic smem (immediate API call; capture-safe, no alloc)
    static bool attr_set = false;
    if (!attr_set) {
        cudaFuncSetAttribute(anfis_fused_kernel,
                             cudaFuncAttributeMaxDynamicSharedMemorySize, SMEM_TOTAL);
        attr_set = true;
    }

    anfis_fused_kernel<<<B_TOTAL / ROWS, THREADS, SMEM_TOTAL>>>(
        x, mf_centers, mf_scales, out_centers, input_rules, output_rules, out);
}

// round 10
// speedup vs baseline: 1.2354x; 1.1532x over previous
#include <cuda_runtime.h>
#include <cuda_fp16.h>

// Problem constants
#define B_TOTAL   16384
#define N_IN      6
#define N_MF      5
#define N_FUZZ    30      // N_IN * N_MF
#define N_RULES   2048
#define N_OUT     2

// Tiling: 128 rows/block, 4 rows per thread (uint2 = 2x half2)
#define THREADS   1024
#define ROWS      128
#define QUADS     32                    // ROWS/4
#define PARTS     32                    // THREADS / QUADS
#define RPP       (N_RULES / PARTS)     // 64 rules per thread

// Shared memory layout (dynamic). Reduction buffer OVERLAPS the rule buffer.
#define SMEM_FUZZ_BYTES   (N_FUZZ * QUADS * 8)           // 7680  (uint2 table)
#define SMEM_RULE_BYTES   (N_RULES * 16)                 // 32768
#define SMEM_RED_BYTES    (QUADS * PARTS * 12 * 4)       // 49152
#define SMEM_TOTAL        (SMEM_FUZZ_BYTES + SMEM_RED_BYTES)   // 56832

// ---- packed f32x2 helpers (Blackwell FFMA2/FADD2 — ptxas won't auto-fuse) ----
__device__ __forceinline__ unsigned long long pack_f32x2(float lo, float hi) {
    unsigned long long r;
    asm("mov.b64 %0, {%1, %2};" : "=l"(r) : "f"(lo), "f"(hi));
    return r;
}
__device__ __forceinline__ void unpack_f32x2(unsigned long long v, float& lo, float& hi) {
    asm("mov.b64 {%0, %1}, %2;" : "=f"(lo), "=f"(hi) : "l"(v));
}
__device__ __forceinline__ void fma_f32x2(unsigned long long& d,
                                          unsigned long long a, unsigned long long b) {
    asm("fma.rn.f32x2 %0, %1, %2, %0;" : "+l"(d) : "l"(a), "l"(b));
}
__device__ __forceinline__ void add_f32x2(unsigned long long& d, unsigned long long a) {
    asm("add.rn.f32x2 %0, %1, %0;" : "+l"(d) : "l"(a));
}

// ---------------------------------------------------------------------------
// Single fused kernel.
// ---------------------------------------------------------------------------
__global__ void __launch_bounds__(THREADS, 1) anfis_fused_kernel(
    const float* __restrict__ x,
    const float* __restrict__ mf_centers,
    const float* __restrict__ mf_scales,
    const float* __restrict__ out_centers,
    const int*   __restrict__ input_rules,
    const int*   __restrict__ output_rules,
    float* __restrict__ out)
{
    extern __shared__ char smem[];
    uint2*  s_fuzz  = reinterpret_cast<uint2*>(smem);                       // [30][32]
    float4* s_rules = reinterpret_cast<float4*>(smem + SMEM_FUZZ_BYTES);    // [2048] (dies after loop)
    float*  s_red   = reinterpret_cast<float*>(smem + SMEM_FUZZ_BYTES);     // overlaps rules

    const int tid  = threadIdx.x;
    const int quad = tid & (QUADS - 1);   // row-quad (0..31)
    const int part = tid >> 5;            // rule partition (0..31); warp-uniform

    // ---- phase 0: pack rules into smem (2 per thread) ----
#pragma unroll
    for (int rr = 0; rr < N_RULES / THREADS; rr++) {
        int r = tid + rr * THREADS;
        unsigned int b0 = 0, b1 = 0;
#pragma unroll
        for (int k = 0; k < 4; k++)
            b0 |= ((unsigned int)input_rules[r * N_IN + k] & 0xFFu) << (8 * k);
#pragma unroll
        for (int k = 0; k < 2; k++)
            b1 |= ((unsigned int)input_rules[r * N_IN + 4 + k] & 0xFFu) << (8 * k);
        float4 rv;
        rv.x = __uint_as_float(b0);
        rv.y = __uint_as_float(b1);
        rv.z = out_centers[output_rules[r * N_OUT + 0]];
        rv.w = out_centers[output_rules[r * N_OUT + 1]];
        s_rules[r] = rv;
    }

    // ---- phase 1: fuzzify — ALL 1024 threads, 3840 values total ----
    {
        __half* fzh = reinterpret_cast<__half*>(s_fuzz);
        const int base_row = blockIdx.x * ROWS;
#pragma unroll
        for (int v = tid; v < N_FUZZ * ROWS; v += THREADS) {
            const int val = v >> 7;          // fuzz value id (0..29)
            const int row = v & (ROWS - 1);  // row in tile
            float xv = x[(base_row + row) * N_IN + val / N_MF];
            float z  = (xv - mf_centers[val]) / mf_scales[val];
            fzh[(val * QUADS + (row >> 2)) * 4 + (row & 3)] = __float2half_rn(__expf(-z * z));
        }
    }
    __syncthreads();

    // ---- phase 2: rule loop with software-pipelined rule fetch ----
    const uint2* fz = s_fuzz + quad;

    unsigned long long l1p0 = 0, l1p1 = 0;   // packed f32x2 accumulators
    unsigned long long d0p0 = 0, d0p1 = 0;
    unsigned long long d1p0 = 0, d1p1 = 0;

    const int rbeg = part * RPP;
    float4 rv = s_rules[rbeg];               // prefetched rule
#pragma unroll 4
    for (int r = 0; r < RPP; r++) {
        // Prefetch next rule (one-past-end read lands in overlapping smem; unused)
        float4 rv_n = s_rules[rbeg + r + 1];

        unsigned int b0 = __float_as_uint(rv.x);
        unsigned int b1 = __float_as_uint(rv.y);

        uint2 g0 = fz[__byte_perm(b0, 0, 0x4440) * QUADS];
        uint2 g1 = fz[__byte_perm(b0, 0, 0x4441) * QUADS];
        uint2 g2 = fz[__byte_perm(b0, 0, 0x4442) * QUADS];
        uint2 g3 = fz[__byte_perm(b0, 0, 0x4443) * QUADS];
        uint2 g4 = fz[__byte_perm(b1, 0, 0x4440) * QUADS];
        uint2 g5 = fz[__byte_perm(b1, 0, 0x4441) * QUADS];

        // tree-shaped min (3 levels) on both packed lanes
        __half2 mx = __hmin2(__hmin2(__hmin2(*(__half2*)&g0.x, *(__half2*)&g1.x),
                                     __hmin2(*(__half2*)&g2.x, *(__half2*)&g3.x)),
                             __hmin2(*(__half2*)&g4.x, *(__half2*)&g5.x));
        __half2 my = __hmin2(__hmin2(__hmin2(*(__half2*)&g0.y, *(__half2*)&g1.y),
                                     __hmin2(*(__half2*)&g2.y, *(__half2*)&g3.y)),
                             __hmin2(*(__half2*)&g4.y, *(__half2*)&g5.y));

        float2 wx = __half22float2(mx);
        float2 wy = __half22float2(my);

        unsigned long long w0 = pack_f32x2(wx.x, wx.y);
        unsigned long long w1 = pack_f32x2(wy.x, wy.y);
        unsigned long long z2 = pack_f32x2(rv.z, rv.z);
        unsigned long long w2 = pack_f32x2(rv.w, rv.w);

        add_f32x2(l1p0, w0);        add_f32x2(l1p1, w1);      // weights > 0
        fma_f32x2(d0p0, w0, z2);    fma_f32x2(d0p1, w1, z2);
        fma_f32x2(d1p0, w0, w2);    fma_f32x2(d1p1, w1, w2);

        rv = rv_n;
    }

    float l1a, l1b, l1c, l1d, d0a, d0b, d0c, d0d, d1a, d1b, d1c, d1d;
    unpack_f32x2(l1p0, l1a, l1b);  unpack_f32x2(l1p1, l1c, l1d);
    unpack_f32x2(d0p0, d0a, d0b);  unpack_f32x2(d0p1, d0c, d0d);
    unpack_f32x2(d1p0, d1a, d1b);  unpack_f32x2(d1p1, d1c, d1d);

    // Rules region is dead; reduction buffer overlaps it.
    __syncthreads();

    // ---- phase 3: cross-partition reduction through smem ----
    {
        float* dst = s_red + (quad * PARTS + part) * 12;
        dst[0] = l1a; dst[1]  = l1b; dst[2]  = l1c; dst[3]  = l1d;
        dst[4] = d0a; dst[5]  = d0b; dst[6]  = d0c; dst[7]  = d0d;
        dst[8] = d1a; dst[9]  = d1b; dst[10] = d1c; dst[11] = d1d;
    }
    __syncthreads();

    if (tid < ROWS) {
        const int row = tid;
        const int q   = row >> 2;
        const int sub = row & 3;
        float L = 0.f, D0 = 0.f, D1 = 0.f;
#pragma unroll
        for (int p = 0; p < PARTS; p++) {
            const float* src = s_red + (q * PARTS + p) * 12;
            L  += src[0 + sub];
            D0 += src[4 + sub];
            D1 += src[8 + sub];
        }
        float inv = 1.0f / fmaxf(L, 1e-12f);
        const int grow = blockIdx.x * ROWS + row;
        out[grow * 2 + 0] = tanhf(D0 * inv) * 4.0f;            // scale 4.0, center 0.0
        out[grow * 2 + 1] = tanhf(D1 * inv) * 0.75f + 0.75f;   // scale 0.75, center 0.75
    }
}

// ---------------------------------------------------------------------------
// Launch contract
// ---------------------------------------------------------------------------
extern "C" void kernel_launch(void* const* d_in, const int* in_sizes, int n_in,
                              void* d_out, int out_size)
{
    const float* x            = (const float*)d_in[0];
    const float* mf_centers   = (const float*)d_in[1];
    const float* mf_scales    = (const float*)d_in[2];
    const float* out_centers  = (const float*)d_in[3];
    const int*   input_rules  = (const int*)d_in[4];
    const int*   output_rules = (const int*)d_in[5];
    float*       out          = (float*)d_out;

    // Opt-in to >48KB dynamic smem (immediate API call; capture-safe, no alloc)
    static bool attr_set = false;
    if (!attr_set) {
        cudaFuncSetAttribute(anfis_fused_kernel,
                             cudaFuncAttributeMaxDynamicSharedMemorySize, SMEM_TOTAL);
        attr_set = true;
    }

    anfis_fused_kernel<<<B_TOTAL / ROWS, THREADS, SMEM_TOTAL>>>(
        x, mf_centers, mf_scales, out_centers, input_rules, output_rules, out);
}